// round 16
// baseline (speedup 1.0000x reference)
#include <cuda_runtime.h>
#include <cuda_fp16.h>
#include <cstdint>

#define NWIN 64
#define HN 8
#define NQ 49
#define MT 50
#define BWIN 4096
#define DIM 256
#define SCALE 0.17677669529663689f

// Bias+mask table in C-fragment order: [w][h][warp 4][nt 7][half 2][lane 32][e 2]
// col>=50 -> -1e30, row>=49 -> 0.  (7.34 MB, L2-resident; verified in R13)
#define BM3_TOTAL (NWIN * HN * 4 * 7 * 2 * 32 * 2)
__device__ float g_bm3[BM3_TOTAL];

__global__ void precompute_bm3(const float* __restrict__ mask,
                               const float* __restrict__ bias_table,
                               const int* __restrict__ rel_index) {
    int i = blockIdx.x * blockDim.x + threadIdx.x;
    if (i >= BM3_TOTAL) return;
    int e    = i & 1;
    int lane = (i >> 1) & 31;
    int half = (i >> 6) & 1;
    int nt   = (i >> 7) % 7;
    int rest = i / (7 << 7);
    int warp = rest & 3;
    int h    = (rest >> 2) & 7;
    int w    = rest >> 5;
    int row = warp * 16 + (lane >> 2) + half * 8;
    int col = nt * 8 + (lane & 3) * 2 + e;
    float v;
    if (col >= MT) v = -1e30f;
    else if (row >= NQ) v = 0.f;
    else {
        v = mask[(w * NQ + row) * MT + col];
        if (col > 0) v += bias_table[rel_index[row * NQ + (col - 1)] * HN + h];
    }
    g_bm3[i] = v;
}

// pack two fp32 into half2 (a -> low, b -> high), rn
__device__ __forceinline__ uint32_t f2h2(float a, float b) {
    uint32_t r;
    asm("cvt.rn.f16x2.f32 %0, %1, %2;" : "=r"(r) : "f"(b), "f"(a));
    return r;
}

__device__ __forceinline__ void mma_f16(float c[4], const uint32_t a[4],
                                        uint32_t b0, uint32_t b1) {
    asm volatile(
        "mma.sync.aligned.m16n8k16.row.col.f32.f16.f16.f32 "
        "{%0,%1,%2,%3}, {%4,%5,%6,%7}, {%8,%9}, {%0,%1,%2,%3};"
        : "+f"(c[0]), "+f"(c[1]), "+f"(c[2]), "+f"(c[3])
        : "r"(a[0]), "r"(a[1]), "r"(a[2]), "r"(a[3]), "r"(b0), "r"(b1));
}

// Smem (18,304 B):
//   [0,     9216)  s_q fp32 [64][36]  (dead after A-fragment build)
//   [9216, 13696)  s_kh half2 [56 keys][20 words]
//   [13696,18304)  s_vt half2 [32 d][36 words]   (kp 28..31 zeroed)
#define OFF_K 9216
#define OFF_V 13696
#define KSTR 20
#define VSTR 36
#define SMEM_BYTES 18304

__global__ void __launch_bounds__(128)
window_attn_h16c(const float* __restrict__ qkv, float* __restrict__ out) {
    __shared__ __align__(16) unsigned char smem_raw[SMEM_BYTES];
    float*    s_q  = (float*)smem_raw;
    uint32_t* s_kh = (uint32_t*)(smem_raw + OFF_K);
    uint32_t* s_vt = (uint32_t*)(smem_raw + OFF_V);

    const int bh = blockIdx.x;
    const int b  = bh >> 3;
    const int h  = bh & 7;
    const int w  = b & (NWIN - 1);
    const float* base = qkv + (size_t)b * MT * 768;
    const int tid = threadIdx.x;

    // ---- stage Q (fp32, pre-scaled, rows >=49 zeroed; row r = token r+1) ----
    for (int i = tid; i < 64 * 8; i += 128) {
        int row = i >> 3, c = i & 7;
        float4 v = make_float4(0.f, 0.f, 0.f, 0.f);
        if (row < NQ) {
            v = *(const float4*)(base + (row + 1) * 768 + h * 32 + c * 4);
            v.x *= SCALE; v.y *= SCALE; v.z *= SCALE; v.w *= SCALE;
        }
        *(float4*)&s_q[row * 36 + c * 4] = v;
    }
    // ---- stage K as half2 pairs along d: s_kh[tok][dp] (toks 50..55 zeroed) ----
    for (int i = tid; i < 56 * 8; i += 128) {
        int tok = i >> 3, c = i & 7;
        float4 kv = make_float4(0.f, 0.f, 0.f, 0.f);
        if (tok < MT)
            kv = *(const float4*)(base + tok * 768 + 256 + h * 32 + c * 4);
        uint2 p; p.x = f2h2(kv.x, kv.y); p.y = f2h2(kv.z, kv.w);
        *(uint2*)&s_kh[tok * KSTR + 2 * c] = p;
    }
    // ---- stage V transposed as half2 pairs along key: s_vt[d][kp] (kp 28..31 zeroed) ----
    for (int i = tid; i < 32 * 8; i += 128) {
        int m = i >> 3, c = i & 7;
        float4 v0 = make_float4(0.f, 0.f, 0.f, 0.f), v1 = v0;
        if (2 * m < MT)
            v0 = *(const float4*)(base + (2 * m) * 768 + 512 + h * 32 + c * 4);
        if (2 * m + 1 < MT)
            v1 = *(const float4*)(base + (2 * m + 1) * 768 + 512 + h * 32 + c * 4);
        s_vt[(4 * c + 0) * VSTR + m] = f2h2(v0.x, v1.x);
        s_vt[(4 * c + 1) * VSTR + m] = f2h2(v0.y, v1.y);
        s_vt[(4 * c + 2) * VSTR + m] = f2h2(v0.z, v1.z);
        s_vt[(4 * c + 3) * VSTR + m] = f2h2(v0.w, v1.w);
    }
    __syncthreads();

    const int warp = tid >> 5, lane = tid & 31;
    const int g = lane >> 2, t = lane & 3;
    const int qrow = warp * 16 + g;

    // ---- Q A-fragments (fp16 hi/lo compensation), built once ----
    uint32_t qhi[2][4], qlo[2][4];
    #pragma unroll
    for (int kc = 0; kc < 2; kc++) {
        #pragma unroll
        for (int r = 0; r < 4; r++) {
            int row = (r & 1) ? (qrow + 8) : qrow;
            int d0  = 16 * kc + 2 * t + ((r >> 1) ? 8 : 0);
            float2 f = *(const float2*)&s_q[row * 36 + d0];
            __half2 H = __floats2half2_rn(f.x, f.y);
            float2 Hf = __half22float2(H);
            qhi[kc][r] = *(uint32_t*)&H;
            qlo[kc][r] = f2h2(f.x - Hf.x, f.y - Hf.y);
        }
    }

    // ---- QK^T: 7 nt x 2 kc x (hi + lo) fp16 MMAs ----
    float c[7][4];
    #pragma unroll
    for (int nt = 0; nt < 7; nt++)
        c[nt][0] = c[nt][1] = c[nt][2] = c[nt][3] = 0.f;

    #pragma unroll
    for (int nt = 0; nt < 7; nt++) {
        const uint32_t* kr = s_kh + (8 * nt + g) * KSTR + t;
        #pragma unroll
        for (int kc = 0; kc < 2; kc++) {
            uint32_t b0 = kr[8 * kc];
            uint32_t b1 = kr[8 * kc + 4];
            mma_f16(c[nt], qhi[kc], b0, b1);
            mma_f16(c[nt], qlo[kc], b0, b1);
        }
    }

    // ---- bias+mask add (coalesced frag-layout LDG), row max, exp, sums ----
    const float2* bmw = (const float2*)g_bm3 +
                        (size_t)(((w * HN + h) * 4 + warp) * 448) + lane;
    float m0 = -1e30f, m1 = -1e30f;
    #pragma unroll
    for (int nt = 0; nt < 7; nt++) {
        float2 mA = bmw[nt * 64];
        float2 mB = bmw[nt * 64 + 32];
        c[nt][0] += mA.x; c[nt][1] += mA.y;
        c[nt][2] += mB.x; c[nt][3] += mB.y;
        m0 = fmaxf(m0, fmaxf(c[nt][0], c[nt][1]));
        m1 = fmaxf(m1, fmaxf(c[nt][2], c[nt][3]));
    }
    m0 = fmaxf(m0, __shfl_xor_sync(0xffffffffu, m0, 1));
    m0 = fmaxf(m0, __shfl_xor_sync(0xffffffffu, m0, 2));
    m1 = fmaxf(m1, __shfl_xor_sync(0xffffffffu, m1, 1));
    m1 = fmaxf(m1, __shfl_xor_sync(0xffffffffu, m1, 2));

    float sum0 = 0.f, sum1 = 0.f;
    #pragma unroll
    for (int nt = 0; nt < 7; nt++) {
        c[nt][0] = __expf(c[nt][0] - m0);
        c[nt][1] = __expf(c[nt][1] - m0);
        c[nt][2] = __expf(c[nt][2] - m1);
        c[nt][3] = __expf(c[nt][3] - m1);
        sum0 += c[nt][0] + c[nt][1];
        sum1 += c[nt][2] + c[nt][3];
    }
    sum0 += __shfl_xor_sync(0xffffffffu, sum0, 1);
    sum0 += __shfl_xor_sync(0xffffffffu, sum0, 2);
    sum1 += __shfl_xor_sync(0xffffffffu, sum1, 1);
    sum1 += __shfl_xor_sync(0xffffffffu, sum1, 2);
    const float inv0 = 1.0f / sum0;
    const float inv1 = 1.0f / sum1;

    // ---- Pack P directly into PV A-fragments (C-frag layout == A-frag layout):
    //      kc chunk keys 16kc..16kc+15 = nt pair {2kc, 2kc+1}.
    //      a0=(g, 2t+16kc) = c[2kc][0,1];  a1=(g+8, ..) = c[2kc][2,3];
    //      a2=(g, 2t+8+16kc) = c[2kc+1][0,1]; a3 = c[2kc+1][2,3].
    //      kc=3 upper half (virtual nt=7, keys 56..63) = 0.
    uint32_t afr[4][4];
    #pragma unroll
    for (int kc = 0; kc < 4; kc++) {
        afr[kc][0] = f2h2(c[2 * kc][0], c[2 * kc][1]);
        afr[kc][1] = f2h2(c[2 * kc][2], c[2 * kc][3]);
        if (kc < 3) {
            afr[kc][2] = f2h2(c[2 * kc + 1][0], c[2 * kc + 1][1]);
            afr[kc][3] = f2h2(c[2 * kc + 1][2], c[2 * kc + 1][3]);
        } else {
            afr[kc][2] = 0u;
            afr[kc][3] = 0u;
        }
    }

    // ---- PV: fp16 m16n8k16, 4 kc x 4 nt; all LDS conflict-free ----
    float o[4][4];
    #pragma unroll
    for (int nt = 0; nt < 4; nt++)
        o[nt][0] = o[nt][1] = o[nt][2] = o[nt][3] = 0.f;

    #pragma unroll
    for (int kc = 0; kc < 4; kc++) {
        #pragma unroll
        for (int nt = 0; nt < 4; nt++) {
            const uint32_t* vr = s_vt + (8 * nt + g) * VSTR + 8 * kc + t;
            mma_f16(o[nt], afr[kc], vr[0], vr[4]);
        }
    }

    // ---- store (normalize here) ----
    if (qrow < NQ) {
        float* orow = out + ((size_t)b * NQ + qrow) * DIM + h * 32;
        #pragma unroll
        for (int nt = 0; nt < 4; nt++) {
            float2 v2; v2.x = o[nt][0] * inv0; v2.y = o[nt][1] * inv0;
            *(float2*)(orow + 8 * nt + 2 * t) = v2;
        }
    }
    if (qrow + 8 < NQ) {
        float* orow = out + ((size_t)b * NQ + qrow + 8) * DIM + h * 32;
        #pragma unroll
        for (int nt = 0; nt < 4; nt++) {
            float2 v2; v2.x = o[nt][2] * inv1; v2.y = o[nt][3] * inv1;
            *(float2*)(orow + 8 * nt + 2 * t) = v2;
        }
    }
}

extern "C" void kernel_launch(void* const* d_in, const int* in_sizes, int n_in,
                              void* d_out, int out_size) {
    const float* qkv        = (const float*)d_in[0];
    const float* mask       = (const float*)d_in[1];
    const float* bias_table = (const float*)d_in[2];
    const int*   rel_index  = (const int*)d_in[3];
    float* out = (float*)d_out;

    precompute_bm3<<<(BM3_TOTAL + 255) / 256, 256>>>(mask, bias_table, rel_index);
    window_attn_h16c<<<BWIN * HN, 128>>>(qkv, out);
}

// round 17
// speedup vs baseline: 1.0996x; 1.0996x over previous
#include <cuda_runtime.h>
#include <cuda_fp16.h>
#include <cstdint>

#define NWIN 64
#define HN 8
#define NQ 49
#define MT 50
#define BWIN 4096
#define DIM 256
#define SCALE 0.17677669529663689f

// Bias+mask table in C-fragment order: [w][h][warp 4][nt 7][half 2][lane 32][e 2]
// col>=50 -> -1e30, row>=49 -> 0.  (7.34 MB, L2-resident; verified in R13)
#define BM3_TOTAL (NWIN * HN * 4 * 7 * 2 * 32 * 2)
__device__ float g_bm3[BM3_TOTAL];

__global__ void precompute_bm3(const float* __restrict__ mask,
                               const float* __restrict__ bias_table,
                               const int* __restrict__ rel_index) {
    int i = blockIdx.x * blockDim.x + threadIdx.x;
    if (i >= BM3_TOTAL) return;
    int e    = i & 1;
    int lane = (i >> 1) & 31;
    int half = (i >> 6) & 1;
    int nt   = (i >> 7) % 7;
    int rest = i / (7 << 7);
    int warp = rest & 3;
    int h    = (rest >> 2) & 7;
    int w    = rest >> 5;
    int row = warp * 16 + (lane >> 2) + half * 8;
    int col = nt * 8 + (lane & 3) * 2 + e;
    float v;
    if (col >= MT) v = -1e30f;
    else if (row >= NQ) v = 0.f;
    else {
        v = mask[(w * NQ + row) * MT + col];
        if (col > 0) v += bias_table[rel_index[row * NQ + (col - 1)] * HN + h];
    }
    g_bm3[i] = v;
}

// pack two fp32 into half2 (a -> low, b -> high), rn
__device__ __forceinline__ uint32_t f2h2(float a, float b) {
    uint32_t r;
    asm("cvt.rn.f16x2.f32 %0, %1, %2;" : "=r"(r) : "f"(b), "f"(a));
    return r;
}

__device__ __forceinline__ void mma_f16(float c[4], const uint32_t a[4],
                                        uint32_t b0, uint32_t b1) {
    asm volatile(
        "mma.sync.aligned.m16n8k16.row.col.f32.f16.f16.f32 "
        "{%0,%1,%2,%3}, {%4,%5,%6,%7}, {%8,%9}, {%0,%1,%2,%3};"
        : "+f"(c[0]), "+f"(c[1]), "+f"(c[2]), "+f"(c[3])
        : "r"(a[0]), "r"(a[1]), "r"(a[2]), "r"(a[3]), "r"(b0), "r"(b1));
}

// Smem (14,208 B), all fragment LDS conflict-free:
//   [0,     5120)  s_qh half2 [64 rows][20 words]  (rows >=49 zeroed, pre-scaled)
//   [5120,  9600)  s_kh half2 [56 keys][20 words]  (keys >=50 zeroed)
//   [9600, 14208)  s_vt half2 [32 d][36 words]     (kp 28..31 zeroed)
#define OFF_K 5120
#define OFF_V 9600
#define QSTR 20
#define KSTR 20
#define VSTR 36
#define SMEM_BYTES 14208

__global__ void __launch_bounds__(128)
window_attn_h16d(const float* __restrict__ qkv, float* __restrict__ out) {
    __shared__ __align__(16) unsigned char smem_raw[SMEM_BYTES];
    uint32_t* s_qh = (uint32_t*)smem_raw;
    uint32_t* s_kh = (uint32_t*)(smem_raw + OFF_K);
    uint32_t* s_vt = (uint32_t*)(smem_raw + OFF_V);

    const int bh = blockIdx.x;
    const int b  = bh >> 3;
    const int h  = bh & 7;
    const int w  = b & (NWIN - 1);
    const float* base = qkv + (size_t)b * MT * 768;
    const int tid = threadIdx.x;

    // ---- stage Q as half2 (pre-scaled; rows >=49 zeroed; row r = token r+1) ----
    for (int i = tid; i < 64 * 8; i += 128) {
        int row = i >> 3, c = i & 7;
        float4 v = make_float4(0.f, 0.f, 0.f, 0.f);
        if (row < NQ) {
            v = *(const float4*)(base + (row + 1) * 768 + h * 32 + c * 4);
            v.x *= SCALE; v.y *= SCALE; v.z *= SCALE; v.w *= SCALE;
        }
        uint2 p; p.x = f2h2(v.x, v.y); p.y = f2h2(v.z, v.w);
        *(uint2*)&s_qh[row * QSTR + 2 * c] = p;
    }
    // ---- stage K as half2 pairs along d (toks 50..55 zeroed) ----
    for (int i = tid; i < 56 * 8; i += 128) {
        int tok = i >> 3, c = i & 7;
        float4 kv = make_float4(0.f, 0.f, 0.f, 0.f);
        if (tok < MT)
            kv = *(const float4*)(base + tok * 768 + 256 + h * 32 + c * 4);
        uint2 p; p.x = f2h2(kv.x, kv.y); p.y = f2h2(kv.z, kv.w);
        *(uint2*)&s_kh[tok * KSTR + 2 * c] = p;
    }
    // ---- stage V transposed as half2 pairs along key (kp 28..31 zeroed) ----
    for (int i = tid; i < 32 * 8; i += 128) {
        int m = i >> 3, c = i & 7;
        float4 v0 = make_float4(0.f, 0.f, 0.f, 0.f), v1 = v0;
        if (2 * m < MT)
            v0 = *(const float4*)(base + (2 * m) * 768 + 512 + h * 32 + c * 4);
        if (2 * m + 1 < MT)
            v1 = *(const float4*)(base + (2 * m + 1) * 768 + 512 + h * 32 + c * 4);
        s_vt[(4 * c + 0) * VSTR + m] = f2h2(v0.x, v1.x);
        s_vt[(4 * c + 1) * VSTR + m] = f2h2(v0.y, v1.y);
        s_vt[(4 * c + 2) * VSTR + m] = f2h2(v0.z, v1.z);
        s_vt[(4 * c + 3) * VSTR + m] = f2h2(v0.w, v1.w);
    }
    __syncthreads();

    const int warp = tid >> 5, lane = tid & 31;
    const int g = lane >> 2, t = lane & 3;
    const int qrow = warp * 16 + g;

    // ---- Q A-fragments: plain fp16 (no compensation), 8 conflict-free LDS.32 ----
    uint32_t qa[2][4];
    #pragma unroll
    for (int kc = 0; kc < 2; kc++) {
        qa[kc][0] = s_qh[qrow * QSTR + 8 * kc + t];
        qa[kc][1] = s_qh[(qrow + 8) * QSTR + 8 * kc + t];
        qa[kc][2] = s_qh[qrow * QSTR + 8 * kc + t + 4];
        qa[kc][3] = s_qh[(qrow + 8) * QSTR + 8 * kc + t + 4];
    }

    // ---- QK^T: 7 nt x 2 kc fp16 MMAs (14 total) ----
    float c[7][4];
    #pragma unroll
    for (int nt = 0; nt < 7; nt++)
        c[nt][0] = c[nt][1] = c[nt][2] = c[nt][3] = 0.f;

    #pragma unroll
    for (int nt = 0; nt < 7; nt++) {
        const uint32_t* kr = s_kh + (8 * nt + g) * KSTR + t;
        #pragma unroll
        for (int kc = 0; kc < 2; kc++) {
            mma_f16(c[nt], qa[kc], kr[8 * kc], kr[8 * kc + 4]);
        }
    }

    // ---- bias+mask add (coalesced frag-layout LDG), row max, exp, sums ----
    const float2* bmw = (const float2*)g_bm3 +
                        (size_t)(((w * HN + h) * 4 + warp) * 448) + lane;
    float m0 = -1e30f, m1 = -1e30f;
    #pragma unroll
    for (int nt = 0; nt < 7; nt++) {
        float2 mA = bmw[nt * 64];
        float2 mB = bmw[nt * 64 + 32];
        c[nt][0] += mA.x; c[nt][1] += mA.y;
        c[nt][2] += mB.x; c[nt][3] += mB.y;
        m0 = fmaxf(m0, fmaxf(c[nt][0], c[nt][1]));
        m1 = fmaxf(m1, fmaxf(c[nt][2], c[nt][3]));
    }
    m0 = fmaxf(m0, __shfl_xor_sync(0xffffffffu, m0, 1));
    m0 = fmaxf(m0, __shfl_xor_sync(0xffffffffu, m0, 2));
    m1 = fmaxf(m1, __shfl_xor_sync(0xffffffffu, m1, 1));
    m1 = fmaxf(m1, __shfl_xor_sync(0xffffffffu, m1, 2));

    float sum0 = 0.f, sum1 = 0.f;
    #pragma unroll
    for (int nt = 0; nt < 7; nt++) {
        c[nt][0] = __expf(c[nt][0] - m0);
        c[nt][1] = __expf(c[nt][1] - m0);
        c[nt][2] = __expf(c[nt][2] - m1);
        c[nt][3] = __expf(c[nt][3] - m1);
        sum0 += c[nt][0] + c[nt][1];
        sum1 += c[nt][2] + c[nt][3];
    }
    sum0 += __shfl_xor_sync(0xffffffffu, sum0, 1);
    sum0 += __shfl_xor_sync(0xffffffffu, sum0, 2);
    sum1 += __shfl_xor_sync(0xffffffffu, sum1, 1);
    sum1 += __shfl_xor_sync(0xffffffffu, sum1, 2);
    const float inv0 = 1.0f / sum0;
    const float inv1 = 1.0f / sum1;

    // ---- Pack P directly into PV A-fragments (C-frag layout == A-frag layout):
    //      kc chunk keys 16kc..16kc+15 = nt pair {2kc, 2kc+1}; kc=3 upper half = 0.
    uint32_t afr[4][4];
    #pragma unroll
    for (int kc = 0; kc < 4; kc++) {
        afr[kc][0] = f2h2(c[2 * kc][0], c[2 * kc][1]);
        afr[kc][1] = f2h2(c[2 * kc][2], c[2 * kc][3]);
        if (kc < 3) {
            afr[kc][2] = f2h2(c[2 * kc + 1][0], c[2 * kc + 1][1]);
            afr[kc][3] = f2h2(c[2 * kc + 1][2], c[2 * kc + 1][3]);
        } else {
            afr[kc][2] = 0u;
            afr[kc][3] = 0u;
        }
    }

    // ---- PV: fp16 m16n8k16, 4 kc x 4 nt; all LDS conflict-free ----
    float o[4][4];
    #pragma unroll
    for (int nt = 0; nt < 4; nt++)
        o[nt][0] = o[nt][1] = o[nt][2] = o[nt][3] = 0.f;

    #pragma unroll
    for (int kc = 0; kc < 4; kc++) {
        #pragma unroll
        for (int nt = 0; nt < 4; nt++) {
            const uint32_t* vr = s_vt + (8 * nt + g) * VSTR + 8 * kc + t;
            mma_f16(o[nt], afr[kc], vr[0], vr[4]);
        }
    }

    // ---- store (normalize here) ----
    if (qrow < NQ) {
        float* orow = out + ((size_t)b * NQ + qrow) * DIM + h * 32;
        #pragma unroll
        for (int nt = 0; nt < 4; nt++) {
            float2 v2; v2.x = o[nt][0] * inv0; v2.y = o[nt][1] * inv0;
            *(float2*)(orow + 8 * nt + 2 * t) = v2;
        }
    }
    if (qrow + 8 < NQ) {
        float* orow = out + ((size_t)b * NQ + qrow + 8) * DIM + h * 32;
        #pragma unroll
        for (int nt = 0; nt < 4; nt++) {
            float2 v2; v2.x = o[nt][2] * inv1; v2.y = o[nt][3] * inv1;
            *(float2*)(orow + 8 * nt + 2 * t) = v2;
        }
    }
}

extern "C" void kernel_launch(void* const* d_in, const int* in_sizes, int n_in,
                              void* d_out, int out_size) {
    const float* qkv        = (const float*)d_in[0];
    const float* mask       = (const float*)d_in[1];
    const float* bias_table = (const float*)d_in[2];
    const int*   rel_index  = (const int*)d_in[3];
    float* out = (float*)d_out;

    precompute_bm3<<<(BM3_TOTAL + 255) / 256, 256>>>(mask, bias_table, rel_index);
    window_attn_h16d<<<BWIN * HN, 128>>>(qkv, out);
}